// round 13
// baseline (speedup 1.0000x reference)
#include <cuda_runtime.h>
#include <cuda_fp16.h>
#include <cstdint>

#define NN   50000
#define EE   800000
#define KIN  256
#define FOUT 128
#define NEG_ATT 0.2f
#define NEG_ACT 0.01f
#define BN_EPS  1e-5f
#define NB   196    // ceil(NN / 256)

// Scratch (static device arrays — no allocations allowed).
// g_deg is zero at module load (BSS) and re-zeroed at the end of final_k.
__device__ __align__(16) __half2 g_hh[(size_t)NN * 64];    // fp16 h mirror
__device__ __align__(16) float   g_s[NN * 4];              // a_src per node/head
__device__ __align__(16) float   g_d[NN * 4];              // a_dst per node/head
__device__ __align__(16) float   g_wself[NN * 4];          // exp(lrelu(s+d)) self weight
__device__ __align__(16) float   g_stats[256];             // col sum[128], sumsq[128]
__device__ int g_deg[NN];                                  // in-degree histogram
__device__ int g_off[NN + 1];                              // CSR offsets
__device__ int g_cur[NN];                                  // scatter cursors
__device__ int g_srcs[EE];                                 // CSR: src per slot
__device__ int g_bsum[256];                                // per-block degree sums
__device__ int g_bpre[256];                                // exclusive block prefixes

// ---------------------------------------------------------------------------
// Kernel 1: h = x @ W^T via 3xTF32 mma + fused attention scoring.
// DOUBLE-BUFFERED smem (96KB dynamic): per iter, MMA reads buf[i&1] while
// convert+STS fills buf[(i+1)&1] — one __syncthreads per 16-k tile, the
// conversion bubble is gone. LDG runs one tile further ahead.
// NOTE: must NOT touch g_deg — the CSR branch runs concurrently.
// ---------------------------------------------------------------------------
__device__ __forceinline__ uint32_t f2tf(float f) {
    uint32_t r; asm("cvt.rna.tf32.f32 %0, %1;" : "=r"(r) : "f"(f)); return r;
}

#define MMA_TF32(D, A0, A1, A2, A3, B0, B1)                                \
    asm volatile("mma.sync.aligned.m16n8k8.row.col.f32.tf32.tf32.f32 "     \
                 "{%0,%1,%2,%3},{%4,%5,%6,%7},{%8,%9},{%0,%1,%2,%3};"      \
                 : "+f"(D[0]), "+f"(D[1]), "+f"(D[2]), "+f"(D[3])          \
                 : "r"(A0), "r"(A1), "r"(A2), "r"(A3), "r"(B0), "r"(B1))

#define RS 48                       // uints per smem row (192 bytes)
#define BUF_U (128 * RS)            // uints per matrix buffer
#define SMEM_BYTES (4 * BUF_U * 4)  // As0,Bs0,As1,Bs1 = 96 KB

__global__ __launch_bounds__(256, 2) void gemm_tc(const float* __restrict__ x,
                                                  const float* __restrict__ W,
                                                  const float* __restrict__ att_src,
                                                  const float* __restrict__ att_dst) {
    extern __shared__ __align__(16) uint32_t smem_dyn[];

    const int tid  = threadIdx.x;
    const int wid  = tid >> 5, lane = tid & 31;
    const int wm   = wid >> 1, wn = wid & 1;     // warp grid 4x2 (M x N)
    const int g    = lane >> 2, t = lane & 3;
    const int row0 = blockIdx.x * 128;

    if (blockIdx.x == 0) g_stats[tid] = 0.f;

    const int sr   = tid >> 1;       // staging row 0..127
    const int sh   = tid & 1;        // k half: 0 or 8
    const int arow = row0 + sr;
    const bool aval = arow < NN;

    float va[8], vb[8];
    float acc[2][8][4];
#pragma unroll
    for (int mt = 0; mt < 2; mt++)
#pragma unroll
        for (int nt = 0; nt < 8; nt++)
#pragma unroll
            for (int i = 0; i < 4; i++) acc[mt][nt][i] = 0.f;

    // stage-load helper (k0 = tile base)
    auto ldg_tile = [&](int k0) {
        float4 a0 = make_float4(0.f,0.f,0.f,0.f), a1 = a0;
        if (aval) {
            a0 = *(const float4*)(x + (size_t)arow * KIN + k0 + sh * 8);
            a1 = *(const float4*)(x + (size_t)arow * KIN + k0 + sh * 8 + 4);
        }
        float4 b0 = *(const float4*)(W + (size_t)sr * KIN + k0 + sh * 8);
        float4 b1 = *(const float4*)(W + (size_t)sr * KIN + k0 + sh * 8 + 4);
        va[0]=a0.x; va[1]=a0.y; va[2]=a0.z; va[3]=a0.w;
        va[4]=a1.x; va[5]=a1.y; va[6]=a1.z; va[7]=a1.w;
        vb[0]=b0.x; vb[1]=b0.y; vb[2]=b0.z; vb[3]=b0.w;
        vb[4]=b1.x; vb[5]=b1.y; vb[6]=b1.z; vb[7]=b1.w;
    };
    auto sts_tile = [&](int buf) {
        uint32_t* Ap = smem_dyn + buf * 2 * BUF_U + sr * RS + sh * 16;
        uint32_t* Bp = Ap + BUF_U;
#pragma unroll
        for (int p = 0; p < 4; p++) {
            uint32_t h0 = f2tf(va[p]), h1 = f2tf(va[p + 4]);
            uint32_t l0 = f2tf(va[p] - __uint_as_float(h0));
            uint32_t l1 = f2tf(va[p + 4] - __uint_as_float(h1));
            *(uint4*)(Ap + p * 4) = make_uint4(h0, h1, l0, l1);
            h0 = f2tf(vb[p]); h1 = f2tf(vb[p + 4]);
            l0 = f2tf(vb[p] - __uint_as_float(h0));
            l1 = f2tf(vb[p + 4] - __uint_as_float(h1));
            *(uint4*)(Bp + p * 4) = make_uint4(h0, h1, l0, l1);
        }
    };

    // prologue: tile 0 into buf0; preload tile 1 into registers
    ldg_tile(0);
    sts_tile(0);
    __syncthreads();
    ldg_tile(16);

    for (int it = 0; it < 16; it++) {
        const uint32_t* As = smem_dyn + (it & 1) * 2 * BUF_U;
        const uint32_t* Bs = As + BUF_U;

#pragma unroll
        for (int blk = 0; blk < 2; blk++) {
            uint32_t ah[2][4], al[2][4];
#pragma unroll
            for (int mt = 0; mt < 2; mt++) {
                int r = wm * 32 + mt * 16 + g;
                uint4 u = *(const uint4*)(As + r * RS + blk * 16 + t * 4);
                uint4 v = *(const uint4*)(As + (r + 8) * RS + blk * 16 + t * 4);
                ah[mt][0] = u.x; ah[mt][1] = v.x; ah[mt][2] = u.y; ah[mt][3] = v.y;
                al[mt][0] = u.z; al[mt][1] = v.z; al[mt][2] = u.w; al[mt][3] = v.w;
            }
#pragma unroll
            for (int nt = 0; nt < 8; nt++) {
                int c = wn * 64 + nt * 8 + g;
                uint4 v = *(const uint4*)(Bs + c * RS + blk * 16 + t * 4);
#pragma unroll
                for (int mt = 0; mt < 2; mt++) {
                    MMA_TF32(acc[mt][nt], ah[mt][0], ah[mt][1], ah[mt][2], ah[mt][3], v.x, v.y);
                    MMA_TF32(acc[mt][nt], ah[mt][0], ah[mt][1], ah[mt][2], ah[mt][3], v.z, v.w);
                    MMA_TF32(acc[mt][nt], al[mt][0], al[mt][1], al[mt][2], al[mt][3], v.x, v.y);
                }
            }
        }

        if (it < 15) sts_tile((it + 1) & 1);      // fill other buffer (overlaps MMA)
        if (it < 14) ldg_tile((it + 2) * 16);     // global load one tile ahead
        if (it < 15) __syncthreads();
    }

    // ---- fused attention scoring ----
    float ps[8], pd[8];
#pragma unroll
    for (int i = 0; i < 8; i++) { ps[i] = 0.f; pd[i] = 0.f; }
#pragma unroll
    for (int nt = 0; nt < 8; nt++) {
        int hl = nt >> 2;
        int head = 2 * wn + hl;
        int c0 = (nt & 3) * 8 + 2 * t;
        float as0 = att_src[head * 32 + c0], as1 = att_src[head * 32 + c0 + 1];
        float ad0 = att_dst[head * 32 + c0], ad1 = att_dst[head * 32 + c0 + 1];
#pragma unroll
        for (int mt = 0; mt < 2; mt++) {
            ps[mt*4 + hl]     = fmaf(acc[mt][nt][0], as0, fmaf(acc[mt][nt][1], as1, ps[mt*4 + hl]));
            pd[mt*4 + hl]     = fmaf(acc[mt][nt][0], ad0, fmaf(acc[mt][nt][1], ad1, pd[mt*4 + hl]));
            ps[mt*4 + 2 + hl] = fmaf(acc[mt][nt][2], as0, fmaf(acc[mt][nt][3], as1, ps[mt*4 + 2 + hl]));
            pd[mt*4 + 2 + hl] = fmaf(acc[mt][nt][2], ad0, fmaf(acc[mt][nt][3], ad1, pd[mt*4 + 2 + hl]));
        }
    }
#pragma unroll
    for (int i = 0; i < 8; i++) {
        ps[i] += __shfl_xor_sync(0xFFFFFFFFu, ps[i], 1);
        ps[i] += __shfl_xor_sync(0xFFFFFFFFu, ps[i], 2);
        pd[i] += __shfl_xor_sync(0xFFFFFFFFu, pd[i], 1);
        pd[i] += __shfl_xor_sync(0xFFFFFFFFu, pd[i], 2);
    }
    if (t == 0) {
#pragma unroll
        for (int mt = 0; mt < 2; mt++)
#pragma unroll
        for (int up = 0; up < 2; up++)
#pragma unroll
        for (int hl = 0; hl < 2; hl++) {
            int gr = row0 + wm * 32 + mt * 16 + up * 8 + g;
            int head = 2 * wn + hl;
            float pss = ps[mt*4 + up*2 + hl], pdd = pd[mt*4 + up*2 + hl];
            if (gr < NN) {
                float e = pss + pdd;
                e = e < 0.f ? NEG_ATT * e : e;
                g_s[gr * 4 + head]     = pss;
                g_d[gr * 4 + head]     = pdd;
                g_wself[gr * 4 + head] = __expf(e);
            }
        }
    }

    // ---- fp16 mirror of h ----
#pragma unroll
    for (int mt = 0; mt < 2; mt++) {
        int r = row0 + wm * 32 + mt * 16 + g;
#pragma unroll
        for (int nt = 0; nt < 8; nt++) {
            int col = wn * 64 + nt * 8 + 2 * t;
            if (r < NN)
                g_hh[(size_t)r * 64 + (col >> 1)] =
                    __floats2half2_rn(acc[mt][nt][0], acc[mt][nt][1]);
            if (r + 8 < NN)
                g_hh[(size_t)(r + 8) * 64 + (col >> 1)] =
                    __floats2half2_rn(acc[mt][nt][2], acc[mt][nt][3]);
        }
    }
}

// ---------------------------------------------------------------------------
// Kernel 2: degree histogram over dst (g_deg pre-zeroed by previous call).
// ---------------------------------------------------------------------------
__global__ __launch_bounds__(256) void hist_k(const int* __restrict__ ei) {
    int e = blockIdx.x * blockDim.x + threadIdx.x;
    if (e < EE) atomicAdd(&g_deg[ei[EE + e]], 1);
}

// ---------------------------------------------------------------------------
// Kernels 3a/3b/3c: parallel 3-phase exclusive scan -> offsets + cursors.
// ---------------------------------------------------------------------------
__global__ __launch_bounds__(256) void blocksum_k() {
    __shared__ int red[256];
    int t = threadIdx.x;
    int i = blockIdx.x * 256 + t;
    red[t] = (i < NN) ? g_deg[i] : 0;
    __syncthreads();
#pragma unroll
    for (int o = 128; o; o >>= 1) {
        if (t < o) red[t] += red[t + o];
        __syncthreads();
    }
    if (t == 0) g_bsum[blockIdx.x] = red[0];
}

__global__ __launch_bounds__(256) void scanblk_k() {
    __shared__ int sc[256];
    int t = threadIdx.x;
    int v = (t < NB) ? g_bsum[t] : 0;
    sc[t] = v;
    __syncthreads();
#pragma unroll
    for (int o = 1; o < 256; o <<= 1) {
        int u = (t >= o) ? sc[t - o] : 0;
        __syncthreads();
        sc[t] += u;
        __syncthreads();
    }
    g_bpre[t] = sc[t] - v;
    if (t == 0) g_off[NN] = EE;
}

__global__ __launch_bounds__(256) void offsets_k() {
    __shared__ int sc[256];
    int t = threadIdx.x;
    int i = blockIdx.x * 256 + t;
    int v = (i < NN) ? g_deg[i] : 0;
    sc[t] = v;
    __syncthreads();
#pragma unroll
    for (int o = 1; o < 256; o <<= 1) {
        int u = (t >= o) ? sc[t - o] : 0;
        __syncthreads();
        sc[t] += u;
        __syncthreads();
    }
    int excl = sc[t] - v + g_bpre[blockIdx.x];
    if (i < NN) { g_off[i] = excl; g_cur[i] = excl; }
}

// ---------------------------------------------------------------------------
// Kernel 4: scatter edges into CSR slots.
// ---------------------------------------------------------------------------
__global__ __launch_bounds__(256) void scatter_k(const int* __restrict__ ei) {
    int e = blockIdx.x * blockDim.x + threadIdx.x;
    if (e >= EE) return;
    int dst = ei[EE + e];
    int pos = atomicAdd(&g_cur[dst], 1);
    g_srcs[pos] = ei[e];
}

// ---------------------------------------------------------------------------
// Kernel 5: gather-aggregate + fused BN stats. One warp per dst node.
// (R11 form — exp in loop; the factorized variant measured slower.)
// ---------------------------------------------------------------------------
__global__ __launch_bounds__(256) void agg_k(const float* __restrict__ bias,
                                             float* __restrict__ out) {
    __shared__ float s_acc[256];
    if (threadIdx.x < 256) s_acc[threadIdx.x] = 0.f;
    __syncthreads();

    int n = (blockIdx.x * blockDim.x + threadIdx.x) >> 5;
    int lane = threadIdx.x & 31;
    const int head = lane >> 3;

    const float d_n = g_d[n * 4 + head];
    float den = g_wself[n * 4 + head];

    const uint2* __restrict__ hh = (const uint2*)g_hh;
    uint2 pself = hh[(size_t)n * 32 + lane];
    float2 sl = __half22float2(*(__half2*)&pself.x);
    float2 shh = __half22float2(*(__half2*)&pself.y);
    float a0 = den * sl.x, a1 = den * sl.y, a2 = den * shh.x, a3 = den * shh.y;

    const int beg = g_off[n];
    const int end = g_off[n + 1];
    for (int b = beg; b < end; b += 32) {
        int idx = b + lane;
        int my = (idx < end) ? g_srcs[idx] : 0;
        int cnt = min(32, end - b);
#pragma unroll 4
        for (int e = 0; e < cnt; e++) {
            int s = __shfl_sync(0xFFFFFFFFu, my, e);
            float sv = g_s[s * 4 + head];
            uint2 p = hh[(size_t)s * 32 + lane];
            float ee = sv + d_n;
            ee = ee < 0.f ? NEG_ATT * ee : ee;
            float w = __expf(ee);
            den += w;
            float2 lo = __half22float2(*(__half2*)&p.x);
            float2 hi = __half22float2(*(__half2*)&p.y);
            a0 = fmaf(w, lo.x, a0); a1 = fmaf(w, lo.y, a1);
            a2 = fmaf(w, hi.x, a2); a3 = fmaf(w, hi.y, a3);
        }
    }

    float rinv = 1.0f / den;
    float4 b4 = *(const float4*)(bias + lane * 4);
    float y0 = fmaf(a0, rinv, b4.x), y1 = fmaf(a1, rinv, b4.y);
    float y2 = fmaf(a2, rinv, b4.z), y3 = fmaf(a3, rinv, b4.w);
    *(float4*)(out + (size_t)n * FOUT + lane * 4) = make_float4(y0, y1, y2, y3);

    int c = lane * 4;
    atomicAdd(&s_acc[c + 0], y0); atomicAdd(&s_acc[128 + c + 0], y0 * y0);
    atomicAdd(&s_acc[c + 1], y1); atomicAdd(&s_acc[128 + c + 1], y1 * y1);
    atomicAdd(&s_acc[c + 2], y2); atomicAdd(&s_acc[128 + c + 2], y2 * y2);
    atomicAdd(&s_acc[c + 3], y3); atomicAdd(&s_acc[128 + c + 3], y3 * y3);
    __syncthreads();
    atomicAdd(&g_stats[threadIdx.x], s_acc[threadIdx.x]);
}

// ---------------------------------------------------------------------------
// Kernel 6: finalize — BN + LeakyReLU(0.01), float4 in place.
// Also re-zeroes g_deg for the NEXT invocation (g_off fully consumed by now).
// ---------------------------------------------------------------------------
__global__ __launch_bounds__(256) void final_k(float* __restrict__ out,
                                               const float* __restrict__ gamma,
                                               const float* __restrict__ beta) {
    size_t idx = (size_t)blockIdx.x * blockDim.x + threadIdx.x;     // over N*32
    if (idx < NN) g_deg[idx] = 0;
    if (idx >= (size_t)NN * 32) return;
    int c = (int)(idx & 31) * 4;
    size_t r = idx >> 5;

    float4 v = *(float4*)(out + r * FOUT + c);
    const float invN = 1.0f / NN;
    float y[4] = {v.x, v.y, v.z, v.w};
#pragma unroll
    for (int j = 0; j < 4; j++) {
        int cc = c + j;
        float mu  = g_stats[cc] * invN;
        float var = fmaf(g_stats[128 + cc], invN, -mu * mu);
        float zz = (y[j] - mu) * rsqrtf(var + BN_EPS) * gamma[cc] + beta[cc];
        y[j] = zz < 0.f ? NEG_ACT * zz : zz;
    }
    *(float4*)(out + r * FOUT + c) = make_float4(y[0], y[1], y[2], y[3]);
}

// ---------------------------------------------------------------------------
// Launch: CSR build forked onto a second stream, overlapping the GEMM.
// ---------------------------------------------------------------------------
extern "C" void kernel_launch(void* const* d_in, const int* in_sizes, int n_in,
                              void* d_out, int out_size) {
    const float* x       = (const float*)d_in[0];
    const int*   ei      = (const int*)  d_in[1];
    const float* W       = (const float*)d_in[2];
    const float* att_src = (const float*)d_in[3];
    const float* att_dst = (const float*)d_in[4];
    const float* bias    = (const float*)d_in[5];
    const float* gamma   = (const float*)d_in[6];
    const float* beta    = (const float*)d_in[7];
    float* out = (float*)d_out;

    static cudaStream_t s2 = nullptr;
    static cudaEvent_t  eFork = nullptr, eJoin = nullptr;
    if (!s2) {
        cudaStreamCreateWithFlags(&s2, cudaStreamNonBlocking);
        cudaEventCreateWithFlags(&eFork, cudaEventDisableTiming);
        cudaEventCreateWithFlags(&eJoin, cudaEventDisableTiming);
        cudaFuncSetAttribute(gemm_tc, cudaFuncAttributeMaxDynamicSharedMemorySize,
                             SMEM_BYTES);
    }

    cudaEventRecord(eFork, 0);
    cudaStreamWaitEvent(s2, eFork, 0);
    hist_k    <<<(EE + 255) / 256, 256, 0, s2>>>(ei);
    blocksum_k<<<NB, 256, 0, s2>>>();
    scanblk_k <<<1, 256, 0, s2>>>();
    offsets_k <<<NB, 256, 0, s2>>>();
    scatter_k <<<(EE + 255) / 256, 256, 0, s2>>>(ei);
    cudaEventRecord(eJoin, s2);

    gemm_tc<<<(NN + 127) / 128, 256, SMEM_BYTES>>>(x, W, att_src, att_dst);

    cudaStreamWaitEvent(0, eJoin, 0);
    agg_k  <<<NN / 8, 256>>>(bias, out);
    final_k<<<(int)(((size_t)NN * 32 + 255) / 256), 256>>>(out, gamma, beta);
}

// round 14
// speedup vs baseline: 1.1240x; 1.1240x over previous
#include <cuda_runtime.h>
#include <cuda_fp16.h>
#include <cstdint>

#define NN   50000
#define EE   800000
#define KIN  256
#define FOUT 128
#define NEG_ATT 0.2f
#define NEG_ACT 0.01f
#define BN_EPS  1e-5f
#define NB   196    // ceil(NN / 256)

// Scratch (static device arrays — no allocations allowed).
// g_deg is zero at module load (BSS) and re-zeroed at the end of final_k.
__device__ __align__(16) __half2 g_hh[(size_t)NN * 64];    // fp16 h mirror
__device__ __align__(16) float   g_s[NN * 4];              // a_src per node/head
__device__ __align__(16) float   g_d[NN * 4];              // a_dst per node/head
__device__ __align__(16) float   g_wself[NN * 4];          // exp(lrelu(s+d)) self weight
__device__ __align__(16) float   g_stats[256];             // col sum[128], sumsq[128]
__device__ int g_deg[NN];                                  // in-degree histogram
__device__ int g_off[NN + 1];                              // CSR offsets
__device__ int g_cur[NN];                                  // scatter cursors
__device__ int g_srcs[EE];                                 // CSR: src per slot
__device__ int g_bsum[256];                                // per-block degree sums
__device__ int g_bpre[256];                                // exclusive block prefixes

// ---------------------------------------------------------------------------
// Kernel 1: h = x @ W^T via 2-term TF32 mma (A full-precision split, B tf32)
// + fused attention scoring. Structure identical to the measured-best R11
// kernel; only the Ahi*Blo term is dropped (W rounded to tf32, ~2^-11).
// NOTE: must NOT touch g_deg — the CSR branch runs concurrently.
// ---------------------------------------------------------------------------
__device__ __forceinline__ uint32_t f2tf(float f) {
    uint32_t r; asm("cvt.rna.tf32.f32 %0, %1;" : "=r"(r) : "f"(f)); return r;
}

#define MMA_TF32(D, A0, A1, A2, A3, B0, B1)                                \
    asm volatile("mma.sync.aligned.m16n8k8.row.col.f32.tf32.tf32.f32 "     \
                 "{%0,%1,%2,%3},{%4,%5,%6,%7},{%8,%9},{%0,%1,%2,%3};"      \
                 : "+f"(D[0]), "+f"(D[1]), "+f"(D[2]), "+f"(D[3])          \
                 : "r"(A0), "r"(A1), "r"(A2), "r"(A3), "r"(B0), "r"(B1))

#define RS 48   // uints per smem row (192 bytes)

__global__ __launch_bounds__(256, 2) void gemm_tc(const float* __restrict__ x,
                                                  const float* __restrict__ W,
                                                  const float* __restrict__ att_src,
                                                  const float* __restrict__ att_dst) {
    __shared__ __align__(16) uint32_t As[128 * RS];
    __shared__ __align__(16) uint32_t Bs[128 * RS];

    const int tid  = threadIdx.x;
    const int wid  = tid >> 5, lane = tid & 31;
    const int wm   = wid >> 1, wn = wid & 1;     // warp grid 4x2 (M x N)
    const int g    = lane >> 2, t = lane & 3;
    const int row0 = blockIdx.x * 128;

    if (blockIdx.x == 0) g_stats[tid] = 0.f;

    const int sr   = tid >> 1;       // staging row 0..127
    const int sh   = tid & 1;        // k half: 0 or 8
    const int arow = row0 + sr;
    const bool aval = arow < NN;

    float va[8], vb[8];
    float acc[2][8][4];
#pragma unroll
    for (int mt = 0; mt < 2; mt++)
#pragma unroll
        for (int nt = 0; nt < 8; nt++)
#pragma unroll
            for (int i = 0; i < 4; i++) acc[mt][nt][i] = 0.f;

    {
        float4 a0 = make_float4(0.f,0.f,0.f,0.f), a1 = a0;
        if (aval) {
            a0 = *(const float4*)(x + (size_t)arow * KIN + sh * 8);
            a1 = *(const float4*)(x + (size_t)arow * KIN + sh * 8 + 4);
        }
        float4 b0 = *(const float4*)(W + (size_t)sr * KIN + sh * 8);
        float4 b1 = *(const float4*)(W + (size_t)sr * KIN + sh * 8 + 4);
        va[0]=a0.x; va[1]=a0.y; va[2]=a0.z; va[3]=a0.w;
        va[4]=a1.x; va[5]=a1.y; va[6]=a1.z; va[7]=a1.w;
        vb[0]=b0.x; vb[1]=b0.y; vb[2]=b0.z; vb[3]=b0.w;
        vb[4]=b1.x; vb[5]=b1.y; vb[6]=b1.z; vb[7]=b1.w;
    }

    uint32_t* Ap = As + sr * RS + sh * 16;
    uint32_t* Bp = Bs + sr * RS + sh * 16;

    for (int it = 0; it < 16; it++) {
        __syncthreads();
#pragma unroll
        for (int p = 0; p < 4; p++) {
            uint32_t h0 = f2tf(va[p]), h1 = f2tf(va[p + 4]);
            uint32_t l0 = f2tf(va[p] - __uint_as_float(h0));
            uint32_t l1 = f2tf(va[p + 4] - __uint_as_float(h1));
            *(uint4*)(Ap + p * 4) = make_uint4(h0, h1, l0, l1);
            h0 = f2tf(vb[p]); h1 = f2tf(vb[p + 4]);
            *(uint4*)(Bp + p * 4) = make_uint4(h0, h1, 0u, 0u);   // Blo unused
        }
        __syncthreads();

        if (it < 15) {
            int k0 = (it + 1) * 16;
            float4 a0 = make_float4(0.f,0.f,0.f,0.f), a1 = a0;
            if (aval) {
                a0 = *(const float4*)(x + (size_t)arow * KIN + k0 + sh * 8);
                a1 = *(const float4*)(x + (size_t)arow * KIN + k0 + sh * 8 + 4);
            }
            float4 b0 = *(const float4*)(W + (size_t)sr * KIN + k0 + sh * 8);
            float4 b1 = *(const float4*)(W + (size_t)sr * KIN + k0 + sh * 8 + 4);
            va[0]=a0.x; va[1]=a0.y; va[2]=a0.z; va[3]=a0.w;
            va[4]=a1.x; va[5]=a1.y; va[6]=a1.z; va[7]=a1.w;
            vb[0]=b0.x; vb[1]=b0.y; vb[2]=b0.z; vb[3]=b0.w;
            vb[4]=b1.x; vb[5]=b1.y; vb[6]=b1.z; vb[7]=b1.w;
        }

#pragma unroll
        for (int blk = 0; blk < 2; blk++) {
            uint32_t ah[2][4], al[2][4];
#pragma unroll
            for (int mt = 0; mt < 2; mt++) {
                int r = wm * 32 + mt * 16 + g;
                uint4 u = *(const uint4*)(As + r * RS + blk * 16 + t * 4);
                uint4 v = *(const uint4*)(As + (r + 8) * RS + blk * 16 + t * 4);
                ah[mt][0] = u.x; ah[mt][1] = v.x; ah[mt][2] = u.y; ah[mt][3] = v.y;
                al[mt][0] = u.z; al[mt][1] = v.z; al[mt][2] = u.w; al[mt][3] = v.w;
            }
#pragma unroll
            for (int nt = 0; nt < 8; nt++) {
                int c = wn * 64 + nt * 8 + g;
                uint4 v = *(const uint4*)(Bs + c * RS + blk * 16 + t * 4);
#pragma unroll
                for (int mt = 0; mt < 2; mt++) {
                    MMA_TF32(acc[mt][nt], ah[mt][0], ah[mt][1], ah[mt][2], ah[mt][3], v.x, v.y);
                    MMA_TF32(acc[mt][nt], al[mt][0], al[mt][1], al[mt][2], al[mt][3], v.x, v.y);
                }
            }
        }
    }

    // ---- fused attention scoring ----
    float ps[8], pd[8];
#pragma unroll
    for (int i = 0; i < 8; i++) { ps[i] = 0.f; pd[i] = 0.f; }
#pragma unroll
    for (int nt = 0; nt < 8; nt++) {
        int hl = nt >> 2;
        int head = 2 * wn + hl;
        int c0 = (nt & 3) * 8 + 2 * t;
        float as0 = att_src[head * 32 + c0], as1 = att_src[head * 32 + c0 + 1];
        float ad0 = att_dst[head * 32 + c0], ad1 = att_dst[head * 32 + c0 + 1];
#pragma unroll
        for (int mt = 0; mt < 2; mt++) {
            ps[mt*4 + hl]     = fmaf(acc[mt][nt][0], as0, fmaf(acc[mt][nt][1], as1, ps[mt*4 + hl]));
            pd[mt*4 + hl]     = fmaf(acc[mt][nt][0], ad0, fmaf(acc[mt][nt][1], ad1, pd[mt*4 + hl]));
            ps[mt*4 + 2 + hl] = fmaf(acc[mt][nt][2], as0, fmaf(acc[mt][nt][3], as1, ps[mt*4 + 2 + hl]));
            pd[mt*4 + 2 + hl] = fmaf(acc[mt][nt][2], ad0, fmaf(acc[mt][nt][3], ad1, pd[mt*4 + 2 + hl]));
        }
    }
#pragma unroll
    for (int i = 0; i < 8; i++) {
        ps[i] += __shfl_xor_sync(0xFFFFFFFFu, ps[i], 1);
        ps[i] += __shfl_xor_sync(0xFFFFFFFFu, ps[i], 2);
        pd[i] += __shfl_xor_sync(0xFFFFFFFFu, pd[i], 1);
        pd[i] += __shfl_xor_sync(0xFFFFFFFFu, pd[i], 2);
    }
    if (t == 0) {
#pragma unroll
        for (int mt = 0; mt < 2; mt++)
#pragma unroll
        for (int up = 0; up < 2; up++)
#pragma unroll
        for (int hl = 0; hl < 2; hl++) {
            int gr = row0 + wm * 32 + mt * 16 + up * 8 + g;
            int head = 2 * wn + hl;
            float pss = ps[mt*4 + up*2 + hl], pdd = pd[mt*4 + up*2 + hl];
            if (gr < NN) {
                float e = pss + pdd;
                e = e < 0.f ? NEG_ATT * e : e;
                g_s[gr * 4 + head]     = pss;
                g_d[gr * 4 + head]     = pdd;
                g_wself[gr * 4 + head] = __expf(e);
            }
        }
    }

    // ---- fp16 mirror of h ----
#pragma unroll
    for (int mt = 0; mt < 2; mt++) {
        int r = row0 + wm * 32 + mt * 16 + g;
#pragma unroll
        for (int nt = 0; nt < 8; nt++) {
            int col = wn * 64 + nt * 8 + 2 * t;
            if (r < NN)
                g_hh[(size_t)r * 64 + (col >> 1)] =
                    __floats2half2_rn(acc[mt][nt][0], acc[mt][nt][1]);
            if (r + 8 < NN)
                g_hh[(size_t)(r + 8) * 64 + (col >> 1)] =
                    __floats2half2_rn(acc[mt][nt][2], acc[mt][nt][3]);
        }
    }
}

// ---------------------------------------------------------------------------
// Kernel 2: degree histogram over dst (g_deg pre-zeroed by previous call).
// ---------------------------------------------------------------------------
__global__ __launch_bounds__(256) void hist_k(const int* __restrict__ ei) {
    int e = blockIdx.x * blockDim.x + threadIdx.x;
    if (e < EE) atomicAdd(&g_deg[ei[EE + e]], 1);
}

// ---------------------------------------------------------------------------
// Kernels 3a/3b/3c: parallel 3-phase exclusive scan -> offsets + cursors.
// ---------------------------------------------------------------------------
__global__ __launch_bounds__(256) void blocksum_k() {
    __shared__ int red[256];
    int t = threadIdx.x;
    int i = blockIdx.x * 256 + t;
    red[t] = (i < NN) ? g_deg[i] : 0;
    __syncthreads();
#pragma unroll
    for (int o = 128; o; o >>= 1) {
        if (t < o) red[t] += red[t + o];
        __syncthreads();
    }
    if (t == 0) g_bsum[blockIdx.x] = red[0];
}

__global__ __launch_bounds__(256) void scanblk_k() {
    __shared__ int sc[256];
    int t = threadIdx.x;
    int v = (t < NB) ? g_bsum[t] : 0;
    sc[t] = v;
    __syncthreads();
#pragma unroll
    for (int o = 1; o < 256; o <<= 1) {
        int u = (t >= o) ? sc[t - o] : 0;
        __syncthreads();
        sc[t] += u;
        __syncthreads();
    }
    g_bpre[t] = sc[t] - v;
    if (t == 0) g_off[NN] = EE;
}

__global__ __launch_bounds__(256) void offsets_k() {
    __shared__ int sc[256];
    int t = threadIdx.x;
    int i = blockIdx.x * 256 + t;
    int v = (i < NN) ? g_deg[i] : 0;
    sc[t] = v;
    __syncthreads();
#pragma unroll
    for (int o = 1; o < 256; o <<= 1) {
        int u = (t >= o) ? sc[t - o] : 0;
        __syncthreads();
        sc[t] += u;
        __syncthreads();
    }
    int excl = sc[t] - v + g_bpre[blockIdx.x];
    if (i < NN) { g_off[i] = excl; g_cur[i] = excl; }
}

// ---------------------------------------------------------------------------
// Kernel 4: scatter edges into CSR slots.
// ---------------------------------------------------------------------------
__global__ __launch_bounds__(256) void scatter_k(const int* __restrict__ ei) {
    int e = blockIdx.x * blockDim.x + threadIdx.x;
    if (e >= EE) return;
    int dst = ei[EE + e];
    int pos = atomicAdd(&g_cur[dst], 1);
    g_srcs[pos] = ei[e];
}

// ---------------------------------------------------------------------------
// Kernel 5: gather-aggregate + fused BN stats. One warp per dst node.
// (R11 form — measured best.)
// ---------------------------------------------------------------------------
__global__ __launch_bounds__(256) void agg_k(const float* __restrict__ bias,
                                             float* __restrict__ out) {
    __shared__ float s_acc[256];
    if (threadIdx.x < 256) s_acc[threadIdx.x] = 0.f;
    __syncthreads();

    int n = (blockIdx.x * blockDim.x + threadIdx.x) >> 5;
    int lane = threadIdx.x & 31;
    const int head = lane >> 3;

    const float d_n = g_d[n * 4 + head];
    float den = g_wself[n * 4 + head];

    const uint2* __restrict__ hh = (const uint2*)g_hh;
    uint2 pself = hh[(size_t)n * 32 + lane];
    float2 sl = __half22float2(*(__half2*)&pself.x);
    float2 shh = __half22float2(*(__half2*)&pself.y);
    float a0 = den * sl.x, a1 = den * sl.y, a2 = den * shh.x, a3 = den * shh.y;

    const int beg = g_off[n];
    const int end = g_off[n + 1];
    for (int b = beg; b < end; b += 32) {
        int idx = b + lane;
        int my = (idx < end) ? g_srcs[idx] : 0;
        int cnt = min(32, end - b);
#pragma unroll 4
        for (int e = 0; e < cnt; e++) {
            int s = __shfl_sync(0xFFFFFFFFu, my, e);
            float sv = g_s[s * 4 + head];
            uint2 p = hh[(size_t)s * 32 + lane];
            float ee = sv + d_n;
            ee = ee < 0.f ? NEG_ATT * ee : ee;
            float w = __expf(ee);
            den += w;
            float2 lo = __half22float2(*(__half2*)&p.x);
            float2 hi = __half22float2(*(__half2*)&p.y);
            a0 = fmaf(w, lo.x, a0); a1 = fmaf(w, lo.y, a1);
            a2 = fmaf(w, hi.x, a2); a3 = fmaf(w, hi.y, a3);
        }
    }

    float rinv = 1.0f / den;
    float4 b4 = *(const float4*)(bias + lane * 4);
    float y0 = fmaf(a0, rinv, b4.x), y1 = fmaf(a1, rinv, b4.y);
    float y2 = fmaf(a2, rinv, b4.z), y3 = fmaf(a3, rinv, b4.w);
    *(float4*)(out + (size_t)n * FOUT + lane * 4) = make_float4(y0, y1, y2, y3);

    int c = lane * 4;
    atomicAdd(&s_acc[c + 0], y0); atomicAdd(&s_acc[128 + c + 0], y0 * y0);
    atomicAdd(&s_acc[c + 1], y1); atomicAdd(&s_acc[128 + c + 1], y1 * y1);
    atomicAdd(&s_acc[c + 2], y2); atomicAdd(&s_acc[128 + c + 2], y2 * y2);
    atomicAdd(&s_acc[c + 3], y3); atomicAdd(&s_acc[128 + c + 3], y3 * y3);
    __syncthreads();
    atomicAdd(&g_stats[threadIdx.x], s_acc[threadIdx.x]);
}

// ---------------------------------------------------------------------------
// Kernel 6: finalize — BN + LeakyReLU(0.01), float4 in place.
// Also re-zeroes g_deg for the NEXT invocation (g_off fully consumed by now).
// ---------------------------------------------------------------------------
__global__ __launch_bounds__(256) void final_k(float* __restrict__ out,
                                               const float* __restrict__ gamma,
                                               const float* __restrict__ beta) {
    size_t idx = (size_t)blockIdx.x * blockDim.x + threadIdx.x;     // over N*32
    if (idx < NN) g_deg[idx] = 0;
    if (idx >= (size_t)NN * 32) return;
    int c = (int)(idx & 31) * 4;
    size_t r = idx >> 5;

    float4 v = *(float4*)(out + r * FOUT + c);
    const float invN = 1.0f / NN;
    float y[4] = {v.x, v.y, v.z, v.w};
#pragma unroll
    for (int j = 0; j < 4; j++) {
        int cc = c + j;
        float mu  = g_stats[cc] * invN;
        float var = fmaf(g_stats[128 + cc], invN, -mu * mu);
        float zz = (y[j] - mu) * rsqrtf(var + BN_EPS) * gamma[cc] + beta[cc];
        y[j] = zz < 0.f ? NEG_ACT * zz : zz;
    }
    *(float4*)(out + r * FOUT + c) = make_float4(y[0], y[1], y[2], y[3]);
}

// ---------------------------------------------------------------------------
// Launch: CSR build forked onto a second stream, overlapping the GEMM.
// ---------------------------------------------------------------------------
extern "C" void kernel_launch(void* const* d_in, const int* in_sizes, int n_in,
                              void* d_out, int out_size) {
    const float* x       = (const float*)d_in[0];
    const int*   ei      = (const int*)  d_in[1];
    const float* W       = (const float*)d_in[2];
    const float* att_src = (const float*)d_in[3];
    const float* att_dst = (const float*)d_in[4];
    const float* bias    = (const float*)d_in[5];
    const float* gamma   = (const float*)d_in[6];
    const float* beta    = (const float*)d_in[7];
    float* out = (float*)d_out;

    static cudaStream_t s2 = nullptr;
    static cudaEvent_t  eFork = nullptr, eJoin = nullptr;
    if (!s2) {
        cudaStreamCreateWithFlags(&s2, cudaStreamNonBlocking);
        cudaEventCreateWithFlags(&eFork, cudaEventDisableTiming);
        cudaEventCreateWithFlags(&eJoin, cudaEventDisableTiming);
    }

    cudaEventRecord(eFork, 0);
    cudaStreamWaitEvent(s2, eFork, 0);
    hist_k    <<<(EE + 255) / 256, 256, 0, s2>>>(ei);
    blocksum_k<<<NB, 256, 0, s2>>>();
    scanblk_k <<<1, 256, 0, s2>>>();
    offsets_k <<<NB, 256, 0, s2>>>();
    scatter_k <<<(EE + 255) / 256, 256, 0, s2>>>(ei);
    cudaEventRecord(eJoin, s2);

    gemm_tc<<<(NN + 127) / 128, 256>>>(x, W, att_src, att_dst);

    cudaStreamWaitEvent(0, eJoin, 0);
    agg_k  <<<NN / 8, 256>>>(bias, out);
    final_k<<<(int)(((size_t)NN * 32 + 255) / 256), 256>>>(out, gamma, beta);
}

// round 15
// speedup vs baseline: 1.1567x; 1.0291x over previous
#include <cuda_runtime.h>
#include <cuda_fp16.h>
#include <cstdint>

#define NN   50000
#define EE   800000
#define KIN  256
#define FOUT 128
#define NEG_ATT 0.2f
#define NEG_ACT 0.01f
#define BN_EPS  1e-5f
#define NB   196    // ceil(NN / 256)

// Scratch (static device arrays — no allocations allowed).
// g_deg is zero at module load (BSS) and re-zeroed at the end of final_k.
__device__ __align__(16) __half2 g_hh[(size_t)NN * 64];    // fp16 h mirror
__device__ __align__(16) float   g_s[NN * 4];              // a_src per node/head
__device__ __align__(16) float   g_d[NN * 4];              // a_dst per node/head
__device__ __align__(16) float   g_wself[NN * 4];          // exp(lrelu(s+d)) self weight
__device__ __align__(16) float   g_stats[256];             // col sum[128], sumsq[128]
__device__ int g_deg[NN];                                  // in-degree histogram
__device__ int g_off[NN + 1];                              // CSR offsets
__device__ int g_cur[NN];                                  // scatter cursors
__device__ int g_srcs[EE];                                 // CSR: src per slot
__device__ int g_bsum[256];                                // per-block degree sums
__device__ int g_bpre[256];                                // exclusive block prefixes

// ---------------------------------------------------------------------------
// Kernel 1: h = x @ W^T via 1-term TF32 mma (both A and W rounded to tf32)
// + fused attention scoring. Structure identical to the measured-best R14
// kernel; the Alo*Bhi term is now dropped as well (error budget verified:
// measured 2.1e-4 fp16-mirror + 2.7e-4 B-tf32 -> predicted ~4.3e-4 total).
// NOTE: must NOT touch g_deg — the CSR branch runs concurrently.
// ---------------------------------------------------------------------------
__device__ __forceinline__ uint32_t f2tf(float f) {
    uint32_t r; asm("cvt.rna.tf32.f32 %0, %1;" : "=r"(r) : "f"(f)); return r;
}

#define MMA_TF32(D, A0, A1, A2, A3, B0, B1)                                \
    asm volatile("mma.sync.aligned.m16n8k8.row.col.f32.tf32.tf32.f32 "     \
                 "{%0,%1,%2,%3},{%4,%5,%6,%7},{%8,%9},{%0,%1,%2,%3};"      \
                 : "+f"(D[0]), "+f"(D[1]), "+f"(D[2]), "+f"(D[3])          \
                 : "r"(A0), "r"(A1), "r"(A2), "r"(A3), "r"(B0), "r"(B1))

#define RS 48   // uints per smem row (192 bytes)

__global__ __launch_bounds__(256, 2) void gemm_tc(const float* __restrict__ x,
                                                  const float* __restrict__ W,
                                                  const float* __restrict__ att_src,
                                                  const float* __restrict__ att_dst) {
    __shared__ __align__(16) uint32_t As[128 * RS];
    __shared__ __align__(16) uint32_t Bs[128 * RS];

    const int tid  = threadIdx.x;
    const int wid  = tid >> 5, lane = tid & 31;
    const int wm   = wid >> 1, wn = wid & 1;     // warp grid 4x2 (M x N)
    const int g    = lane >> 2, t = lane & 3;
    const int row0 = blockIdx.x * 128;

    if (blockIdx.x == 0) g_stats[tid] = 0.f;

    const int sr   = tid >> 1;       // staging row 0..127
    const int sh   = tid & 1;        // k half: 0 or 8
    const int arow = row0 + sr;
    const bool aval = arow < NN;

    float va[8], vb[8];
    float acc[2][8][4];
#pragma unroll
    for (int mt = 0; mt < 2; mt++)
#pragma unroll
        for (int nt = 0; nt < 8; nt++)
#pragma unroll
            for (int i = 0; i < 4; i++) acc[mt][nt][i] = 0.f;

    {
        float4 a0 = make_float4(0.f,0.f,0.f,0.f), a1 = a0;
        if (aval) {
            a0 = *(const float4*)(x + (size_t)arow * KIN + sh * 8);
            a1 = *(const float4*)(x + (size_t)arow * KIN + sh * 8 + 4);
        }
        float4 b0 = *(const float4*)(W + (size_t)sr * KIN + sh * 8);
        float4 b1 = *(const float4*)(W + (size_t)sr * KIN + sh * 8 + 4);
        va[0]=a0.x; va[1]=a0.y; va[2]=a0.z; va[3]=a0.w;
        va[4]=a1.x; va[5]=a1.y; va[6]=a1.z; va[7]=a1.w;
        vb[0]=b0.x; vb[1]=b0.y; vb[2]=b0.z; vb[3]=b0.w;
        vb[4]=b1.x; vb[5]=b1.y; vb[6]=b1.z; vb[7]=b1.w;
    }

    uint32_t* Ap = As + sr * RS + sh * 16;
    uint32_t* Bp = Bs + sr * RS + sh * 16;

    for (int it = 0; it < 16; it++) {
        __syncthreads();
#pragma unroll
        for (int p = 0; p < 4; p++) {
            uint32_t h0 = f2tf(va[p]), h1 = f2tf(va[p + 4]);
            *(uint4*)(Ap + p * 4) = make_uint4(h0, h1, 0u, 0u);   // Alo unused
            h0 = f2tf(vb[p]); h1 = f2tf(vb[p + 4]);
            *(uint4*)(Bp + p * 4) = make_uint4(h0, h1, 0u, 0u);   // Blo unused
        }
        __syncthreads();

        if (it < 15) {
            int k0 = (it + 1) * 16;
            float4 a0 = make_float4(0.f,0.f,0.f,0.f), a1 = a0;
            if (aval) {
                a0 = *(const float4*)(x + (size_t)arow * KIN + k0 + sh * 8);
                a1 = *(const float4*)(x + (size_t)arow * KIN + k0 + sh * 8 + 4);
            }
            float4 b0 = *(const float4*)(W + (size_t)sr * KIN + k0 + sh * 8);
            float4 b1 = *(const float4*)(W + (size_t)sr * KIN + k0 + sh * 8 + 4);
            va[0]=a0.x; va[1]=a0.y; va[2]=a0.z; va[3]=a0.w;
            va[4]=a1.x; va[5]=a1.y; va[6]=a1.z; va[7]=a1.w;
            vb[0]=b0.x; vb[1]=b0.y; vb[2]=b0.z; vb[3]=b0.w;
            vb[4]=b1.x; vb[5]=b1.y; vb[6]=b1.z; vb[7]=b1.w;
        }

#pragma unroll
        for (int blk = 0; blk < 2; blk++) {
            uint32_t ah[2][4];
#pragma unroll
            for (int mt = 0; mt < 2; mt++) {
                int r = wm * 32 + mt * 16 + g;
                uint4 u = *(const uint4*)(As + r * RS + blk * 16 + t * 4);
                uint4 v = *(const uint4*)(As + (r + 8) * RS + blk * 16 + t * 4);
                ah[mt][0] = u.x; ah[mt][1] = v.x; ah[mt][2] = u.y; ah[mt][3] = v.y;
            }
#pragma unroll
            for (int nt = 0; nt < 8; nt++) {
                int c = wn * 64 + nt * 8 + g;
                uint4 v = *(const uint4*)(Bs + c * RS + blk * 16 + t * 4);
#pragma unroll
                for (int mt = 0; mt < 2; mt++) {
                    MMA_TF32(acc[mt][nt], ah[mt][0], ah[mt][1], ah[mt][2], ah[mt][3], v.x, v.y);
                }
            }
        }
    }

    // ---- fused attention scoring ----
    float ps[8], pd[8];
#pragma unroll
    for (int i = 0; i < 8; i++) { ps[i] = 0.f; pd[i] = 0.f; }
#pragma unroll
    for (int nt = 0; nt < 8; nt++) {
        int hl = nt >> 2;
        int head = 2 * wn + hl;
        int c0 = (nt & 3) * 8 + 2 * t;
        float as0 = att_src[head * 32 + c0], as1 = att_src[head * 32 + c0 + 1];
        float ad0 = att_dst[head * 32 + c0], ad1 = att_dst[head * 32 + c0 + 1];
#pragma unroll
        for (int mt = 0; mt < 2; mt++) {
            ps[mt*4 + hl]     = fmaf(acc[mt][nt][0], as0, fmaf(acc[mt][nt][1], as1, ps[mt*4 + hl]));
            pd[mt*4 + hl]     = fmaf(acc[mt][nt][0], ad0, fmaf(acc[mt][nt][1], ad1, pd[mt*4 + hl]));
            ps[mt*4 + 2 + hl] = fmaf(acc[mt][nt][2], as0, fmaf(acc[mt][nt][3], as1, ps[mt*4 + 2 + hl]));
            pd[mt*4 + 2 + hl] = fmaf(acc[mt][nt][2], ad0, fmaf(acc[mt][nt][3], ad1, pd[mt*4 + 2 + hl]));
        }
    }
#pragma unroll
    for (int i = 0; i < 8; i++) {
        ps[i] += __shfl_xor_sync(0xFFFFFFFFu, ps[i], 1);
        ps[i] += __shfl_xor_sync(0xFFFFFFFFu, ps[i], 2);
        pd[i] += __shfl_xor_sync(0xFFFFFFFFu, pd[i], 1);
        pd[i] += __shfl_xor_sync(0xFFFFFFFFu, pd[i], 2);
    }
    if (t == 0) {
#pragma unroll
        for (int mt = 0; mt < 2; mt++)
#pragma unroll
        for (int up = 0; up < 2; up++)
#pragma unroll
        for (int hl = 0; hl < 2; hl++) {
            int gr = row0 + wm * 32 + mt * 16 + up * 8 + g;
            int head = 2 * wn + hl;
            float pss = ps[mt*4 + up*2 + hl], pdd = pd[mt*4 + up*2 + hl];
            if (gr < NN) {
                float e = pss + pdd;
                e = e < 0.f ? NEG_ATT * e : e;
                g_s[gr * 4 + head]     = pss;
                g_d[gr * 4 + head]     = pdd;
                g_wself[gr * 4 + head] = __expf(e);
            }
        }
    }

    // ---- fp16 mirror of h ----
#pragma unroll
    for (int mt = 0; mt < 2; mt++) {
        int r = row0 + wm * 32 + mt * 16 + g;
#pragma unroll
        for (int nt = 0; nt < 8; nt++) {
            int col = wn * 64 + nt * 8 + 2 * t;
            if (r < NN)
                g_hh[(size_t)r * 64 + (col >> 1)] =
                    __floats2half2_rn(acc[mt][nt][0], acc[mt][nt][1]);
            if (r + 8 < NN)
                g_hh[(size_t)(r + 8) * 64 + (col >> 1)] =
                    __floats2half2_rn(acc[mt][nt][2], acc[mt][nt][3]);
        }
    }
}

// ---------------------------------------------------------------------------
// Kernel 2: degree histogram over dst (g_deg pre-zeroed by previous call).
// ---------------------------------------------------------------------------
__global__ __launch_bounds__(256) void hist_k(const int* __restrict__ ei) {
    int e = blockIdx.x * blockDim.x + threadIdx.x;
    if (e < EE) atomicAdd(&g_deg[ei[EE + e]], 1);
}

// ---------------------------------------------------------------------------
// Kernels 3a/3b/3c: parallel 3-phase exclusive scan -> offsets + cursors.
// ---------------------------------------------------------------------------
__global__ __launch_bounds__(256) void blocksum_k() {
    __shared__ int red[256];
    int t = threadIdx.x;
    int i = blockIdx.x * 256 + t;
    red[t] = (i < NN) ? g_deg[i] : 0;
    __syncthreads();
#pragma unroll
    for (int o = 128; o; o >>= 1) {
        if (t < o) red[t] += red[t + o];
        __syncthreads();
    }
    if (t == 0) g_bsum[blockIdx.x] = red[0];
}

__global__ __launch_bounds__(256) void scanblk_k() {
    __shared__ int sc[256];
    int t = threadIdx.x;
    int v = (t < NB) ? g_bsum[t] : 0;
    sc[t] = v;
    __syncthreads();
#pragma unroll
    for (int o = 1; o < 256; o <<= 1) {
        int u = (t >= o) ? sc[t - o] : 0;
        __syncthreads();
        sc[t] += u;
        __syncthreads();
    }
    g_bpre[t] = sc[t] - v;
    if (t == 0) g_off[NN] = EE;
}

__global__ __launch_bounds__(256) void offsets_k() {
    __shared__ int sc[256];
    int t = threadIdx.x;
    int i = blockIdx.x * 256 + t;
    int v = (i < NN) ? g_deg[i] : 0;
    sc[t] = v;
    __syncthreads();
#pragma unroll
    for (int o = 1; o < 256; o <<= 1) {
        int u = (t >= o) ? sc[t - o] : 0;
        __syncthreads();
        sc[t] += u;
        __syncthreads();
    }
    int excl = sc[t] - v + g_bpre[blockIdx.x];
    if (i < NN) { g_off[i] = excl; g_cur[i] = excl; }
}

// ---------------------------------------------------------------------------
// Kernel 4: scatter edges into CSR slots.
// ---------------------------------------------------------------------------
__global__ __launch_bounds__(256) void scatter_k(const int* __restrict__ ei) {
    int e = blockIdx.x * blockDim.x + threadIdx.x;
    if (e >= EE) return;
    int dst = ei[EE + e];
    int pos = atomicAdd(&g_cur[dst], 1);
    g_srcs[pos] = ei[e];
}

// ---------------------------------------------------------------------------
// Kernel 5: gather-aggregate + fused BN stats. One warp per dst node.
// (R11 form — measured best.)
// ---------------------------------------------------------------------------
__global__ __launch_bounds__(256) void agg_k(const float* __restrict__ bias,
                                             float* __restrict__ out) {
    __shared__ float s_acc[256];
    if (threadIdx.x < 256) s_acc[threadIdx.x] = 0.f;
    __syncthreads();

    int n = (blockIdx.x * blockDim.x + threadIdx.x) >> 5;
    int lane = threadIdx.x & 31;
    const int head = lane >> 3;

    const float d_n = g_d[n * 4 + head];
    float den = g_wself[n * 4 + head];

    const uint2* __restrict__ hh = (const uint2*)g_hh;
    uint2 pself = hh[(size_t)n * 32 + lane];
    float2 sl = __half22float2(*(__half2*)&pself.x);
    float2 shh = __half22float2(*(__half2*)&pself.y);
    float a0 = den * sl.x, a1 = den * sl.y, a2 = den * shh.x, a3 = den * shh.y;

    const int beg = g_off[n];
    const int end = g_off[n + 1];
    for (int b = beg; b < end; b += 32) {
        int idx = b + lane;
        int my = (idx < end) ? g_srcs[idx] : 0;
        int cnt = min(32, end - b);
#pragma unroll 4
        for (int e = 0; e < cnt; e++) {
            int s = __shfl_sync(0xFFFFFFFFu, my, e);
            float sv = g_s[s * 4 + head];
            uint2 p = hh[(size_t)s * 32 + lane];
            float ee = sv + d_n;
            ee = ee < 0.f ? NEG_ATT * ee : ee;
            float w = __expf(ee);
            den += w;
            float2 lo = __half22float2(*(__half2*)&p.x);
            float2 hi = __half22float2(*(__half2*)&p.y);
            a0 = fmaf(w, lo.x, a0); a1 = fmaf(w, lo.y, a1);
            a2 = fmaf(w, hi.x, a2); a3 = fmaf(w, hi.y, a3);
        }
    }

    float rinv = 1.0f / den;
    float4 b4 = *(const float4*)(bias + lane * 4);
    float y0 = fmaf(a0, rinv, b4.x), y1 = fmaf(a1, rinv, b4.y);
    float y2 = fmaf(a2, rinv, b4.z), y3 = fmaf(a3, rinv, b4.w);
    *(float4*)(out + (size_t)n * FOUT + lane * 4) = make_float4(y0, y1, y2, y3);

    int c = lane * 4;
    atomicAdd(&s_acc[c + 0], y0); atomicAdd(&s_acc[128 + c + 0], y0 * y0);
    atomicAdd(&s_acc[c + 1], y1); atomicAdd(&s_acc[128 + c + 1], y1 * y1);
    atomicAdd(&s_acc[c + 2], y2); atomicAdd(&s_acc[128 + c + 2], y2 * y2);
    atomicAdd(&s_acc[c + 3], y3); atomicAdd(&s_acc[128 + c + 3], y3 * y3);
    __syncthreads();
    atomicAdd(&g_stats[threadIdx.x], s_acc[threadIdx.x]);
}

// ---------------------------------------------------------------------------
// Kernel 6: finalize — BN + LeakyReLU(0.01), float4 in place.
// Also re-zeroes g_deg for the NEXT invocation (g_off fully consumed by now).
// ---------------------------------------------------------------------------
__global__ __launch_bounds__(256) void final_k(float* __restrict__ out,
                                               const float* __restrict__ gamma,
                                               const float* __restrict__ beta) {
    size_t idx = (size_t)blockIdx.x * blockDim.x + threadIdx.x;     // over N*32
    if (idx < NN) g_deg[idx] = 0;
    if (idx >= (size_t)NN * 32) return;
    int c = (int)(idx & 31) * 4;
    size_t r = idx >> 5;

    float4 v = *(float4*)(out + r * FOUT + c);
    const float invN = 1.0f / NN;
    float y[4] = {v.x, v.y, v.z, v.w};
#pragma unroll
    for (int j = 0; j < 4; j++) {
        int cc = c + j;
        float mu  = g_stats[cc] * invN;
        float var = fmaf(g_stats[128 + cc], invN, -mu * mu);
        float zz = (y[j] - mu) * rsqrtf(var + BN_EPS) * gamma[cc] + beta[cc];
        y[j] = zz < 0.f ? NEG_ACT * zz : zz;
    }
    *(float4*)(out + r * FOUT + c) = make_float4(y[0], y[1], y[2], y[3]);
}

// ---------------------------------------------------------------------------
// Launch: CSR build forked onto a second stream, overlapping the GEMM.
// ---------------------------------------------------------------------------
extern "C" void kernel_launch(void* const* d_in, const int* in_sizes, int n_in,
                              void* d_out, int out_size) {
    const float* x       = (const float*)d_in[0];
    const int*   ei      = (const int*)  d_in[1];
    const float* W       = (const float*)d_in[2];
    const float* att_src = (const float*)d_in[3];
    const float* att_dst = (const float*)d_in[4];
    const float* bias    = (const float*)d_in[5];
    const float* gamma   = (const float*)d_in[6];
    const float* beta    = (const float*)d_in[7];
    float* out = (float*)d_out;

    static cudaStream_t s2 = nullptr;
    static cudaEvent_t  eFork = nullptr, eJoin = nullptr;
    if (!s2) {
        cudaStreamCreateWithFlags(&s2, cudaStreamNonBlocking);
        cudaEventCreateWithFlags(&eFork, cudaEventDisableTiming);
        cudaEventCreateWithFlags(&eJoin, cudaEventDisableTiming);
    }

    cudaEventRecord(eFork, 0);
    cudaStreamWaitEvent(s2, eFork, 0);
    hist_k    <<<(EE + 255) / 256, 256, 0, s2>>>(ei);
    blocksum_k<<<NB, 256, 0, s2>>>();
    scanblk_k <<<1, 256, 0, s2>>>();
    offsets_k <<<NB, 256, 0, s2>>>();
    scatter_k <<<(EE + 255) / 256, 256, 0, s2>>>(ei);
    cudaEventRecord(eJoin, s2);

    gemm_tc<<<(NN + 127) / 128, 256>>>(x, W, att_src, att_dst);

    cudaStreamWaitEvent(0, eJoin, 0);
    agg_k  <<<NN / 8, 256>>>(bias, out);
    final_k<<<(int)(((size_t)NN * 32 + 255) / 256), 256>>>(out, gamma, beta);
}

// round 16
// speedup vs baseline: 1.1710x; 1.0124x over previous
#include <cuda_runtime.h>
#include <cuda_fp16.h>
#include <cstdint>

#define NN   50000
#define EE   800000
#define KIN  256
#define FOUT 128
#define NEG_ATT 0.2f
#define NEG_ACT 0.01f
#define BN_EPS  1e-5f
#define NB   196    // ceil(NN / 256)

// Scratch (static device arrays — no allocations allowed).
// g_deg is zero at module load (BSS) and re-zeroed at the end of final_k.
__device__ __align__(16) __half2 g_hh[(size_t)NN * 64];    // fp16 h mirror
__device__ __align__(16) float   g_s[NN * 4];              // a_src per node/head
__device__ __align__(16) float   g_d[NN * 4];              // a_dst per node/head
__device__ __align__(16) float   g_wself[NN * 4];          // exp(lrelu(s+d)) self weight
__device__ __align__(16) float   g_stats[256];             // col sum[128], sumsq[128]
__device__ int g_deg[NN];                                  // in-degree histogram
__device__ int g_off[NN + 1];                              // CSR offsets
__device__ int g_cur[NN];                                  // scatter cursors
__device__ int g_srcs[EE];                                 // CSR: src per slot
__device__ int g_bsum[256];                                // per-block degree sums
__device__ int g_bpre[256];                                // exclusive block prefixes

// ---------------------------------------------------------------------------
// Kernel 1: h = x @ W^T via 1-term TF32 mma + fused attention scoring.
// Same layout/addresses as the measured-best R15 kernel, but all staging
// stores and fragment loads are uint2 (the .z/.w slots were dead zeros) —
// halves STS and LDS bytes with bit-identical math.
// NOTE: must NOT touch g_deg — the CSR branch runs concurrently.
// ---------------------------------------------------------------------------
__device__ __forceinline__ uint32_t f2tf(float f) {
    uint32_t r; asm("cvt.rna.tf32.f32 %0, %1;" : "=r"(r) : "f"(f)); return r;
}

#define MMA_TF32(D, A0, A1, A2, A3, B0, B1)                                \
    asm volatile("mma.sync.aligned.m16n8k8.row.col.f32.tf32.tf32.f32 "     \
                 "{%0,%1,%2,%3},{%4,%5,%6,%7},{%8,%9},{%0,%1,%2,%3};"      \
                 : "+f"(D[0]), "+f"(D[1]), "+f"(D[2]), "+f"(D[3])          \
                 : "r"(A0), "r"(A1), "r"(A2), "r"(A3), "r"(B0), "r"(B1))

#define RS 48   // uints per smem row (192 bytes) — geometry unchanged

__global__ __launch_bounds__(256, 2) void gemm_tc(const float* __restrict__ x,
                                                  const float* __restrict__ W,
                                                  const float* __restrict__ att_src,
                                                  const float* __restrict__ att_dst) {
    __shared__ __align__(16) uint32_t As[128 * RS];
    __shared__ __align__(16) uint32_t Bs[128 * RS];

    const int tid  = threadIdx.x;
    const int wid  = tid >> 5, lane = tid & 31;
    const int wm   = wid >> 1, wn = wid & 1;     // warp grid 4x2 (M x N)
    const int g    = lane >> 2, t = lane & 3;
    const int row0 = blockIdx.x * 128;

    if (blockIdx.x == 0) g_stats[tid] = 0.f;

    const int sr   = tid >> 1;       // staging row 0..127
    const int sh   = tid & 1;        // k half: 0 or 8
    const int arow = row0 + sr;
    const bool aval = arow < NN;

    float va[8], vb[8];
    float acc[2][8][4];
#pragma unroll
    for (int mt = 0; mt < 2; mt++)
#pragma unroll
        for (int nt = 0; nt < 8; nt++)
#pragma unroll
            for (int i = 0; i < 4; i++) acc[mt][nt][i] = 0.f;

    {
        float4 a0 = make_float4(0.f,0.f,0.f,0.f), a1 = a0;
        if (aval) {
            a0 = *(const float4*)(x + (size_t)arow * KIN + sh * 8);
            a1 = *(const float4*)(x + (size_t)arow * KIN + sh * 8 + 4);
        }
        float4 b0 = *(const float4*)(W + (size_t)sr * KIN + sh * 8);
        float4 b1 = *(const float4*)(W + (size_t)sr * KIN + sh * 8 + 4);
        va[0]=a0.x; va[1]=a0.y; va[2]=a0.z; va[3]=a0.w;
        va[4]=a1.x; va[5]=a1.y; va[6]=a1.z; va[7]=a1.w;
        vb[0]=b0.x; vb[1]=b0.y; vb[2]=b0.z; vb[3]=b0.w;
        vb[4]=b1.x; vb[5]=b1.y; vb[6]=b1.z; vb[7]=b1.w;
    }

    uint32_t* Ap = As + sr * RS + sh * 16;
    uint32_t* Bp = Bs + sr * RS + sh * 16;

    for (int it = 0; it < 16; it++) {
        __syncthreads();
#pragma unroll
        for (int p = 0; p < 4; p++) {
            uint32_t h0 = f2tf(va[p]), h1 = f2tf(va[p + 4]);
            *(uint2*)(Ap + p * 4) = make_uint2(h0, h1);     // 8B store, .z/.w dead
            h0 = f2tf(vb[p]); h1 = f2tf(vb[p + 4]);
            *(uint2*)(Bp + p * 4) = make_uint2(h0, h1);
        }
        __syncthreads();

        if (it < 15) {
            int k0 = (it + 1) * 16;
            float4 a0 = make_float4(0.f,0.f,0.f,0.f), a1 = a0;
            if (aval) {
                a0 = *(const float4*)(x + (size_t)arow * KIN + k0 + sh * 8);
                a1 = *(const float4*)(x + (size_t)arow * KIN + k0 + sh * 8 + 4);
            }
            float4 b0 = *(const float4*)(W + (size_t)sr * KIN + k0 + sh * 8);
            float4 b1 = *(const float4*)(W + (size_t)sr * KIN + k0 + sh * 8 + 4);
            va[0]=a0.x; va[1]=a0.y; va[2]=a0.z; va[3]=a0.w;
            va[4]=a1.x; va[5]=a1.y; va[6]=a1.z; va[7]=a1.w;
            vb[0]=b0.x; vb[1]=b0.y; vb[2]=b0.z; vb[3]=b0.w;
            vb[4]=b1.x; vb[5]=b1.y; vb[6]=b1.z; vb[7]=b1.w;
        }

#pragma unroll
        for (int blk = 0; blk < 2; blk++) {
            uint32_t ah[2][4];
#pragma unroll
            for (int mt = 0; mt < 2; mt++) {
                int r = wm * 32 + mt * 16 + g;
                uint2 u = *(const uint2*)(As + r * RS + blk * 16 + t * 4);
                uint2 v = *(const uint2*)(As + (r + 8) * RS + blk * 16 + t * 4);
                ah[mt][0] = u.x; ah[mt][1] = v.x; ah[mt][2] = u.y; ah[mt][3] = v.y;
            }
#pragma unroll
            for (int nt = 0; nt < 8; nt++) {
                int c = wn * 64 + nt * 8 + g;
                uint2 v = *(const uint2*)(Bs + c * RS + blk * 16 + t * 4);
#pragma unroll
                for (int mt = 0; mt < 2; mt++) {
                    MMA_TF32(acc[mt][nt], ah[mt][0], ah[mt][1], ah[mt][2], ah[mt][3], v.x, v.y);
                }
            }
        }
    }

    // ---- fused attention scoring ----
    float ps[8], pd[8];
#pragma unroll
    for (int i = 0; i < 8; i++) { ps[i] = 0.f; pd[i] = 0.f; }
#pragma unroll
    for (int nt = 0; nt < 8; nt++) {
        int hl = nt >> 2;
        int head = 2 * wn + hl;
        int c0 = (nt & 3) * 8 + 2 * t;
        float as0 = att_src[head * 32 + c0], as1 = att_src[head * 32 + c0 + 1];
        float ad0 = att_dst[head * 32 + c0], ad1 = att_dst[head * 32 + c0 + 1];
#pragma unroll
        for (int mt = 0; mt < 2; mt++) {
            ps[mt*4 + hl]     = fmaf(acc[mt][nt][0], as0, fmaf(acc[mt][nt][1], as1, ps[mt*4 + hl]));
            pd[mt*4 + hl]     = fmaf(acc[mt][nt][0], ad0, fmaf(acc[mt][nt][1], ad1, pd[mt*4 + hl]));
            ps[mt*4 + 2 + hl] = fmaf(acc[mt][nt][2], as0, fmaf(acc[mt][nt][3], as1, ps[mt*4 + 2 + hl]));
            pd[mt*4 + 2 + hl] = fmaf(acc[mt][nt][2], ad0, fmaf(acc[mt][nt][3], ad1, pd[mt*4 + 2 + hl]));
        }
    }
#pragma unroll
    for (int i = 0; i < 8; i++) {
        ps[i] += __shfl_xor_sync(0xFFFFFFFFu, ps[i], 1);
        ps[i] += __shfl_xor_sync(0xFFFFFFFFu, ps[i], 2);
        pd[i] += __shfl_xor_sync(0xFFFFFFFFu, pd[i], 1);
        pd[i] += __shfl_xor_sync(0xFFFFFFFFu, pd[i], 2);
    }
    if (t == 0) {
#pragma unroll
        for (int mt = 0; mt < 2; mt++)
#pragma unroll
        for (int up = 0; up < 2; up++)
#pragma unroll
        for (int hl = 0; hl < 2; hl++) {
            int gr = row0 + wm * 32 + mt * 16 + up * 8 + g;
            int head = 2 * wn + hl;
            float pss = ps[mt*4 + up*2 + hl], pdd = pd[mt*4 + up*2 + hl];
            if (gr < NN) {
                float e = pss + pdd;
                e = e < 0.f ? NEG_ATT * e : e;
                g_s[gr * 4 + head]     = pss;
                g_d[gr * 4 + head]     = pdd;
                g_wself[gr * 4 + head] = __expf(e);
            }
        }
    }

    // ---- fp16 mirror of h ----
#pragma unroll
    for (int mt = 0; mt < 2; mt++) {
        int r = row0 + wm * 32 + mt * 16 + g;
#pragma unroll
        for (int nt = 0; nt < 8; nt++) {
            int col = wn * 64 + nt * 8 + 2 * t;
            if (r < NN)
                g_hh[(size_t)r * 64 + (col >> 1)] =
                    __floats2half2_rn(acc[mt][nt][0], acc[mt][nt][1]);
            if (r + 8 < NN)
                g_hh[(size_t)(r + 8) * 64 + (col >> 1)] =
                    __floats2half2_rn(acc[mt][nt][2], acc[mt][nt][3]);
        }
    }
}

// ---------------------------------------------------------------------------
// Kernel 2: degree histogram over dst (g_deg pre-zeroed by previous call).
// ---------------------------------------------------------------------------
__global__ __launch_bounds__(256) void hist_k(const int* __restrict__ ei) {
    int e = blockIdx.x * blockDim.x + threadIdx.x;
    if (e < EE) atomicAdd(&g_deg[ei[EE + e]], 1);
}

// ---------------------------------------------------------------------------
// Kernels 3a/3b/3c: parallel 3-phase exclusive scan -> offsets + cursors.
// ---------------------------------------------------------------------------
__global__ __launch_bounds__(256) void blocksum_k() {
    __shared__ int red[256];
    int t = threadIdx.x;
    int i = blockIdx.x * 256 + t;
    red[t] = (i < NN) ? g_deg[i] : 0;
    __syncthreads();
#pragma unroll
    for (int o = 128; o; o >>= 1) {
        if (t < o) red[t] += red[t + o];
        __syncthreads();
    }
    if (t == 0) g_bsum[blockIdx.x] = red[0];
}

__global__ __launch_bounds__(256) void scanblk_k() {
    __shared__ int sc[256];
    int t = threadIdx.x;
    int v = (t < NB) ? g_bsum[t] : 0;
    sc[t] = v;
    __syncthreads();
#pragma unroll
    for (int o = 1; o < 256; o <<= 1) {
        int u = (t >= o) ? sc[t - o] : 0;
        __syncthreads();
        sc[t] += u;
        __syncthreads();
    }
    g_bpre[t] = sc[t] - v;
    if (t == 0) g_off[NN] = EE;
}

__global__ __launch_bounds__(256) void offsets_k() {
    __shared__ int sc[256];
    int t = threadIdx.x;
    int i = blockIdx.x * 256 + t;
    int v = (i < NN) ? g_deg[i] : 0;
    sc[t] = v;
    __syncthreads();
#pragma unroll
    for (int o = 1; o < 256; o <<= 1) {
        int u = (t >= o) ? sc[t - o] : 0;
        __syncthreads();
        sc[t] += u;
        __syncthreads();
    }
    int excl = sc[t] - v + g_bpre[blockIdx.x];
    if (i < NN) { g_off[i] = excl; g_cur[i] = excl; }
}

// ---------------------------------------------------------------------------
// Kernel 4: scatter edges into CSR slots.
// ---------------------------------------------------------------------------
__global__ __launch_bounds__(256) void scatter_k(const int* __restrict__ ei) {
    int e = blockIdx.x * blockDim.x + threadIdx.x;
    if (e >= EE) return;
    int dst = ei[EE + e];
    int pos = atomicAdd(&g_cur[dst], 1);
    g_srcs[pos] = ei[e];
}

// ---------------------------------------------------------------------------
// Kernel 5: gather-aggregate + fused BN stats. One warp per dst node.
// (R11 form — measured best.)
// ---------------------------------------------------------------------------
__global__ __launch_bounds__(256) void agg_k(const float* __restrict__ bias,
                                             float* __restrict__ out) {
    __shared__ float s_acc[256];
    if (threadIdx.x < 256) s_acc[threadIdx.x] = 0.f;
    __syncthreads();

    int n = (blockIdx.x * blockDim.x + threadIdx.x) >> 5;
    int lane = threadIdx.x & 31;
    const int head = lane >> 3;

    const float d_n = g_d[n * 4 + head];
    float den = g_wself[n * 4 + head];

    const uint2* __restrict__ hh = (const uint2*)g_hh;
    uint2 pself = hh[(size_t)n * 32 + lane];
    float2 sl = __half22float2(*(__half2*)&pself.x);
    float2 shh = __half22float2(*(__half2*)&pself.y);
    float a0 = den * sl.x, a1 = den * sl.y, a2 = den * shh.x, a3 = den * shh.y;

    const int beg = g_off[n];
    const int end = g_off[n + 1];
    for (int b = beg; b < end; b += 32) {
        int idx = b + lane;
        int my = (idx < end) ? g_srcs[idx] : 0;
        int cnt = min(32, end - b);
#pragma unroll 4
        for (int e = 0; e < cnt; e++) {
            int s = __shfl_sync(0xFFFFFFFFu, my, e);
            float sv = g_s[s * 4 + head];
            uint2 p = hh[(size_t)s * 32 + lane];
            float ee = sv + d_n;
            ee = ee < 0.f ? NEG_ATT * ee : ee;
            float w = __expf(ee);
            den += w;
            float2 lo = __half22float2(*(__half2*)&p.x);
            float2 hi = __half22float2(*(__half2*)&p.y);
            a0 = fmaf(w, lo.x, a0); a1 = fmaf(w, lo.y, a1);
            a2 = fmaf(w, hi.x, a2); a3 = fmaf(w, hi.y, a3);
        }
    }

    float rinv = 1.0f / den;
    float4 b4 = *(const float4*)(bias + lane * 4);
    float y0 = fmaf(a0, rinv, b4.x), y1 = fmaf(a1, rinv, b4.y);
    float y2 = fmaf(a2, rinv, b4.z), y3 = fmaf(a3, rinv, b4.w);
    *(float4*)(out + (size_t)n * FOUT + lane * 4) = make_float4(y0, y1, y2, y3);

    int c = lane * 4;
    atomicAdd(&s_acc[c + 0], y0); atomicAdd(&s_acc[128 + c + 0], y0 * y0);
    atomicAdd(&s_acc[c + 1], y1); atomicAdd(&s_acc[128 + c + 1], y1 * y1);
    atomicAdd(&s_acc[c + 2], y2); atomicAdd(&s_acc[128 + c + 2], y2 * y2);
    atomicAdd(&s_acc[c + 3], y3); atomicAdd(&s_acc[128 + c + 3], y3 * y3);
    __syncthreads();
    atomicAdd(&g_stats[threadIdx.x], s_acc[threadIdx.x]);
}

// ---------------------------------------------------------------------------
// Kernel 6: finalize — BN + LeakyReLU(0.01), float4 in place.
// Also re-zeroes g_deg for the NEXT invocation (g_off fully consumed by now).
// ---------------------------------------------------------------------------
__global__ __launch_bounds__(256) void final_k(float* __restrict__ out,
                                               const float* __restrict__ gamma,
                                               const float* __restrict__ beta) {
    size_t idx = (size_t)blockIdx.x * blockDim.x + threadIdx.x;     // over N*32
    if (idx < NN) g_deg[idx] = 0;
    if (idx >= (size_t)NN * 32) return;
    int c = (int)(idx & 31) * 4;
    size_t r = idx >> 5;

    float4 v = *(float4*)(out + r * FOUT + c);
    const float invN = 1.0f / NN;
    float y[4] = {v.x, v.y, v.z, v.w};
#pragma unroll
    for (int j = 0; j < 4; j++) {
        int cc = c + j;
        float mu  = g_stats[cc] * invN;
        float var = fmaf(g_stats[128 + cc], invN, -mu * mu);
        float zz = (y[j] - mu) * rsqrtf(var + BN_EPS) * gamma[cc] + beta[cc];
        y[j] = zz < 0.f ? NEG_ACT * zz : zz;
    }
    *(float4*)(out + r * FOUT + c) = make_float4(y[0], y[1], y[2], y[3]);
}

// ---------------------------------------------------------------------------
// Launch: CSR build forked onto a second stream, overlapping the GEMM.
// ---------------------------------------------------------------------------
extern "C" void kernel_launch(void* const* d_in, const int* in_sizes, int n_in,
                              void* d_out, int out_size) {
    const float* x       = (const float*)d_in[0];
    const int*   ei      = (const int*)  d_in[1];
    const float* W       = (const float*)d_in[2];
    const float* att_src = (const float*)d_in[3];
    const float* att_dst = (const float*)d_in[4];
    const float* bias    = (const float*)d_in[5];
    const float* gamma   = (const float*)d_in[6];
    const float* beta    = (const float*)d_in[7];
    float* out = (float*)d_out;

    static cudaStream_t s2 = nullptr;
    static cudaEvent_t  eFork = nullptr, eJoin = nullptr;
    if (!s2) {
        cudaStreamCreateWithFlags(&s2, cudaStreamNonBlocking);
        cudaEventCreateWithFlags(&eFork, cudaEventDisableTiming);
        cudaEventCreateWithFlags(&eJoin, cudaEventDisableTiming);
    }

    cudaEventRecord(eFork, 0);
    cudaStreamWaitEvent(s2, eFork, 0);
    hist_k    <<<(EE + 255) / 256, 256, 0, s2>>>(ei);
    blocksum_k<<<NB, 256, 0, s2>>>();
    scanblk_k <<<1, 256, 0, s2>>>();
    offsets_k <<<NB, 256, 0, s2>>>();
    scatter_k <<<(EE + 255) / 256, 256, 0, s2>>>(ei);
    cudaEventRecord(eJoin, s2);

    gemm_tc<<<(NN + 127) / 128, 256>>>(x, W, att_src, att_dst);

    cudaStreamWaitEvent(0, eJoin, 0);
    agg_k  <<<NN / 8, 256>>>(bias, out);
    final_k<<<(int)(((size_t)NN * 32 + 255) / 256), 256>>>(out, gamma, beta);
}

// round 17
// speedup vs baseline: 1.2114x; 1.0346x over previous
#include <cuda_runtime.h>
#include <cuda_fp16.h>
#include <cstdint>

#define NN   50000
#define EE   800000
#define KIN  256
#define FOUT 128
#define NEG_ATT 0.2f
#define NEG_ACT 0.01f
#define BN_EPS  1e-5f
#define NB   196    // ceil(NN / 256)

// Scratch (static device arrays — no allocations allowed).
// g_deg is zero at module load (BSS) and re-zeroed at the end of final_k.
__device__ __align__(16) __half2 g_hh[(size_t)NN * 64];    // fp16 h mirror
__device__ __align__(16) float   g_s[NN * 4];              // a_src per node/head
__device__ __align__(16) float   g_d[NN * 4];              // a_dst per node/head
__device__ __align__(16) float   g_wself[NN * 4];          // exp(lrelu(s+d)) self weight
__device__ __align__(16) float   g_stats[256];             // col sum[128], sumsq[128]
__device__ int g_deg[NN];                                  // in-degree histogram
__device__ int g_off[NN + 1];                              // CSR offsets
__device__ int g_cur[NN];                                  // scatter cursors
__device__ int g_srcs[EE];                                 // CSR: src per slot
__device__ int g_bsum[256];                                // per-block degree sums
__device__ int g_bpre[256];                                // exclusive block prefixes

// ---------------------------------------------------------------------------
// Kernel 1: h = x @ W^T via 1-term TF32 mma + fused attention scoring.
// (R16 measured-best form: uint2 staging/fragments, RS=48 geometry.)
// NOTE: must NOT touch g_deg — the CSR branch runs concurrently.
// ---------------------------------------------------------------------------
__device__ __forceinline__ uint32_t f2tf(float f) {
    uint32_t r; asm("cvt.rna.tf32.f32 %0, %1;" : "=r"(r) : "f"(f)); return r;
}

#define MMA_TF32(D, A0, A1, A2, A3, B0, B1)                                \
    asm volatile("mma.sync.aligned.m16n8k8.row.col.f32.tf32.tf32.f32 "     \
                 "{%0,%1,%2,%3},{%4,%5,%6,%7},{%8,%9},{%0,%1,%2,%3};"      \
                 : "+f"(D[0]), "+f"(D[1]), "+f"(D[2]), "+f"(D[3])          \
                 : "r"(A0), "r"(A1), "r"(A2), "r"(A3), "r"(B0), "r"(B1))

#define RS 48   // uints per smem row (192 bytes)

__global__ __launch_bounds__(256, 2) void gemm_tc(const float* __restrict__ x,
                                                  const float* __restrict__ W,
                                                  const float* __restrict__ att_src,
                                                  const float* __restrict__ att_dst) {
    __shared__ __align__(16) uint32_t As[128 * RS];
    __shared__ __align__(16) uint32_t Bs[128 * RS];

    const int tid  = threadIdx.x;
    const int wid  = tid >> 5, lane = tid & 31;
    const int wm   = wid >> 1, wn = wid & 1;     // warp grid 4x2 (M x N)
    const int g    = lane >> 2, t = lane & 3;
    const int row0 = blockIdx.x * 128;

    if (blockIdx.x == 0) g_stats[tid] = 0.f;

    const int sr   = tid >> 1;       // staging row 0..127
    const int sh   = tid & 1;        // k half: 0 or 8
    const int arow = row0 + sr;
    const bool aval = arow < NN;

    float va[8], vb[8];
    float acc[2][8][4];
#pragma unroll
    for (int mt = 0; mt < 2; mt++)
#pragma unroll
        for (int nt = 0; nt < 8; nt++)
#pragma unroll
            for (int i = 0; i < 4; i++) acc[mt][nt][i] = 0.f;

    {
        float4 a0 = make_float4(0.f,0.f,0.f,0.f), a1 = a0;
        if (aval) {
            a0 = *(const float4*)(x + (size_t)arow * KIN + sh * 8);
            a1 = *(const float4*)(x + (size_t)arow * KIN + sh * 8 + 4);
        }
        float4 b0 = *(const float4*)(W + (size_t)sr * KIN + sh * 8);
        float4 b1 = *(const float4*)(W + (size_t)sr * KIN + sh * 8 + 4);
        va[0]=a0.x; va[1]=a0.y; va[2]=a0.z; va[3]=a0.w;
        va[4]=a1.x; va[5]=a1.y; va[6]=a1.z; va[7]=a1.w;
        vb[0]=b0.x; vb[1]=b0.y; vb[2]=b0.z; vb[3]=b0.w;
        vb[4]=b1.x; vb[5]=b1.y; vb[6]=b1.z; vb[7]=b1.w;
    }

    uint32_t* Ap = As + sr * RS + sh * 16;
    uint32_t* Bp = Bs + sr * RS + sh * 16;

    for (int it = 0; it < 16; it++) {
        __syncthreads();
#pragma unroll
        for (int p = 0; p < 4; p++) {
            uint32_t h0 = f2tf(va[p]), h1 = f2tf(va[p + 4]);
            *(uint2*)(Ap + p * 4) = make_uint2(h0, h1);
            h0 = f2tf(vb[p]); h1 = f2tf(vb[p + 4]);
            *(uint2*)(Bp + p * 4) = make_uint2(h0, h1);
        }
        __syncthreads();

        if (it < 15) {
            int k0 = (it + 1) * 16;
            float4 a0 = make_float4(0.f,0.f,0.f,0.f), a1 = a0;
            if (aval) {
                a0 = *(const float4*)(x + (size_t)arow * KIN + k0 + sh * 8);
                a1 = *(const float4*)(x + (size_t)arow * KIN + k0 + sh * 8 + 4);
            }
            float4 b0 = *(const float4*)(W + (size_t)sr * KIN + k0 + sh * 8);
            float4 b1 = *(const float4*)(W + (size_t)sr * KIN + k0 + sh * 8 + 4);
            va[0]=a0.x; va[1]=a0.y; va[2]=a0.z; va[3]=a0.w;
            va[4]=a1.x; va[5]=a1.y; va[6]=a1.z; va[7]=a1.w;
            vb[0]=b0.x; vb[1]=b0.y; vb[2]=b0.z; vb[3]=b0.w;
            vb[4]=b1.x; vb[5]=b1.y; vb[6]=b1.z; vb[7]=b1.w;
        }

#pragma unroll
        for (int blk = 0; blk < 2; blk++) {
            uint32_t ah[2][4];
#pragma unroll
            for (int mt = 0; mt < 2; mt++) {
                int r = wm * 32 + mt * 16 + g;
                uint2 u = *(const uint2*)(As + r * RS + blk * 16 + t * 4);
                uint2 v = *(const uint2*)(As + (r + 8) * RS + blk * 16 + t * 4);
                ah[mt][0] = u.x; ah[mt][1] = v.x; ah[mt][2] = u.y; ah[mt][3] = v.y;
            }
#pragma unroll
            for (int nt = 0; nt < 8; nt++) {
                int c = wn * 64 + nt * 8 + g;
                uint2 v = *(const uint2*)(Bs + c * RS + blk * 16 + t * 4);
#pragma unroll
                for (int mt = 0; mt < 2; mt++) {
                    MMA_TF32(acc[mt][nt], ah[mt][0], ah[mt][1], ah[mt][2], ah[mt][3], v.x, v.y);
                }
            }
        }
    }

    // ---- fused attention scoring ----
    float ps[8], pd[8];
#pragma unroll
    for (int i = 0; i < 8; i++) { ps[i] = 0.f; pd[i] = 0.f; }
#pragma unroll
    for (int nt = 0; nt < 8; nt++) {
        int hl = nt >> 2;
        int head = 2 * wn + hl;
        int c0 = (nt & 3) * 8 + 2 * t;
        float as0 = att_src[head * 32 + c0], as1 = att_src[head * 32 + c0 + 1];
        float ad0 = att_dst[head * 32 + c0], ad1 = att_dst[head * 32 + c0 + 1];
#pragma unroll
        for (int mt = 0; mt < 2; mt++) {
            ps[mt*4 + hl]     = fmaf(acc[mt][nt][0], as0, fmaf(acc[mt][nt][1], as1, ps[mt*4 + hl]));
            pd[mt*4 + hl]     = fmaf(acc[mt][nt][0], ad0, fmaf(acc[mt][nt][1], ad1, pd[mt*4 + hl]));
            ps[mt*4 + 2 + hl] = fmaf(acc[mt][nt][2], as0, fmaf(acc[mt][nt][3], as1, ps[mt*4 + 2 + hl]));
            pd[mt*4 + 2 + hl] = fmaf(acc[mt][nt][2], ad0, fmaf(acc[mt][nt][3], ad1, pd[mt*4 + 2 + hl]));
        }
    }
#pragma unroll
    for (int i = 0; i < 8; i++) {
        ps[i] += __shfl_xor_sync(0xFFFFFFFFu, ps[i], 1);
        ps[i] += __shfl_xor_sync(0xFFFFFFFFu, ps[i], 2);
        pd[i] += __shfl_xor_sync(0xFFFFFFFFu, pd[i], 1);
        pd[i] += __shfl_xor_sync(0xFFFFFFFFu, pd[i], 2);
    }
    if (t == 0) {
#pragma unroll
        for (int mt = 0; mt < 2; mt++)
#pragma unroll
        for (int up = 0; up < 2; up++)
#pragma unroll
        for (int hl = 0; hl < 2; hl++) {
            int gr = row0 + wm * 32 + mt * 16 + up * 8 + g;
            int head = 2 * wn + hl;
            float pss = ps[mt*4 + up*2 + hl], pdd = pd[mt*4 + up*2 + hl];
            if (gr < NN) {
                float e = pss + pdd;
                e = e < 0.f ? NEG_ATT * e : e;
                g_s[gr * 4 + head]     = pss;
                g_d[gr * 4 + head]     = pdd;
                g_wself[gr * 4 + head] = __expf(e);
            }
        }
    }

    // ---- fp16 mirror of h ----
#pragma unroll
    for (int mt = 0; mt < 2; mt++) {
        int r = row0 + wm * 32 + mt * 16 + g;
#pragma unroll
        for (int nt = 0; nt < 8; nt++) {
            int col = wn * 64 + nt * 8 + 2 * t;
            if (r < NN)
                g_hh[(size_t)r * 64 + (col >> 1)] =
                    __floats2half2_rn(acc[mt][nt][0], acc[mt][nt][1]);
            if (r + 8 < NN)
                g_hh[(size_t)(r + 8) * 64 + (col >> 1)] =
                    __floats2half2_rn(acc[mt][nt][2], acc[mt][nt][3]);
        }
    }
}

// ---------------------------------------------------------------------------
// Kernel 2: degree histogram over dst (g_deg pre-zeroed by previous call).
// ---------------------------------------------------------------------------
__global__ __launch_bounds__(256) void hist_k(const int* __restrict__ ei) {
    int e = blockIdx.x * blockDim.x + threadIdx.x;
    if (e < EE) atomicAdd(&g_deg[ei[EE + e]], 1);
}

// ---------------------------------------------------------------------------
// Kernels 3a/3b/3c: parallel 3-phase exclusive scan -> offsets + cursors.
// ---------------------------------------------------------------------------
__global__ __launch_bounds__(256) void blocksum_k() {
    __shared__ int red[256];
    int t = threadIdx.x;
    int i = blockIdx.x * 256 + t;
    red[t] = (i < NN) ? g_deg[i] : 0;
    __syncthreads();
#pragma unroll
    for (int o = 128; o; o >>= 1) {
        if (t < o) red[t] += red[t + o];
        __syncthreads();
    }
    if (t == 0) g_bsum[blockIdx.x] = red[0];
}

__global__ __launch_bounds__(256) void scanblk_k() {
    __shared__ int sc[256];
    int t = threadIdx.x;
    int v = (t < NB) ? g_bsum[t] : 0;
    sc[t] = v;
    __syncthreads();
#pragma unroll
    for (int o = 1; o < 256; o <<= 1) {
        int u = (t >= o) ? sc[t - o] : 0;
        __syncthreads();
        sc[t] += u;
        __syncthreads();
    }
    g_bpre[t] = sc[t] - v;
    if (t == 0) g_off[NN] = EE;
}

__global__ __launch_bounds__(256) void offsets_k() {
    __shared__ int sc[256];
    int t = threadIdx.x;
    int i = blockIdx.x * 256 + t;
    int v = (i < NN) ? g_deg[i] : 0;
    sc[t] = v;
    __syncthreads();
#pragma unroll
    for (int o = 1; o < 256; o <<= 1) {
        int u = (t >= o) ? sc[t - o] : 0;
        __syncthreads();
        sc[t] += u;
        __syncthreads();
    }
    int excl = sc[t] - v + g_bpre[blockIdx.x];
    if (i < NN) { g_off[i] = excl; g_cur[i] = excl; }
}

// ---------------------------------------------------------------------------
// Kernel 4: scatter edges into CSR slots.
// ---------------------------------------------------------------------------
__global__ __launch_bounds__(256) void scatter_k(const int* __restrict__ ei) {
    int e = blockIdx.x * blockDim.x + threadIdx.x;
    if (e >= EE) return;
    int dst = ei[EE + e];
    int pos = atomicAdd(&g_cur[dst], 1);
    g_srcs[pos] = ei[e];
}

// ---------------------------------------------------------------------------
// Kernel 5: gather-aggregate + fused BN stats. One warp per dst node.
// Stats epilogue v2: per-warp non-atomic smem slabs (each warp owns its
// node's values) + tree sum over the 8 warps — replaces the 8-way
// same-address shared atomics that cost ~14 us (measured R10 delta).
// ---------------------------------------------------------------------------
__global__ __launch_bounds__(256) void agg_k(const float* __restrict__ bias,
                                             float* __restrict__ out) {
    __shared__ float s_sum[8][128];   // [warp][column]
    __shared__ float s_sq[8][128];

    int n = (blockIdx.x * blockDim.x + threadIdx.x) >> 5;
    int lane = threadIdx.x & 31;
    int wid = threadIdx.x >> 5;
    const int head = lane >> 3;

    const float d_n = g_d[n * 4 + head];
    float den = g_wself[n * 4 + head];

    const uint2* __restrict__ hh = (const uint2*)g_hh;
    uint2 pself = hh[(size_t)n * 32 + lane];
    float2 sl = __half22float2(*(__half2*)&pself.x);
    float2 shh = __half22float2(*(__half2*)&pself.y);
    float a0 = den * sl.x, a1 = den * sl.y, a2 = den * shh.x, a3 = den * shh.y;

    const int beg = g_off[n];
    const int end = g_off[n + 1];
    for (int b = beg; b < end; b += 32) {
        int idx = b + lane;
        int my = (idx < end) ? g_srcs[idx] : 0;
        int cnt = min(32, end - b);
#pragma unroll 4
        for (int e = 0; e < cnt; e++) {
            int s = __shfl_sync(0xFFFFFFFFu, my, e);
            float sv = g_s[s * 4 + head];
            uint2 p = hh[(size_t)s * 32 + lane];
            float ee = sv + d_n;
            ee = ee < 0.f ? NEG_ATT * ee : ee;
            float w = __expf(ee);
            den += w;
            float2 lo = __half22float2(*(__half2*)&p.x);
            float2 hi = __half22float2(*(__half2*)&p.y);
            a0 = fmaf(w, lo.x, a0); a1 = fmaf(w, lo.y, a1);
            a2 = fmaf(w, hi.x, a2); a3 = fmaf(w, hi.y, a3);
        }
    }

    float rinv = 1.0f / den;
    float4 b4 = *(const float4*)(bias + lane * 4);
    float y0 = fmaf(a0, rinv, b4.x), y1 = fmaf(a1, rinv, b4.y);
    float y2 = fmaf(a2, rinv, b4.z), y3 = fmaf(a3, rinv, b4.w);
    *(float4*)(out + (size_t)n * FOUT + lane * 4) = make_float4(y0, y1, y2, y3);

    // conflict-free per-warp stats slabs (warp owns row wid; lanes own cols)
    int c = lane * 4;
    *(float4*)&s_sum[wid][c] = make_float4(y0, y1, y2, y3);
    *(float4*)&s_sq[wid][c]  = make_float4(y0 * y0, y1 * y1, y2 * y2, y3 * y3);
    __syncthreads();

    // 256 threads -> 256 outputs: tid<128 sums s_sum col, tid>=128 sums s_sq
    int tidx = threadIdx.x;
    const float* base = (tidx < 128) ? &s_sum[0][tidx] : &s_sq[0][tidx - 128];
    float tot = 0.f;
#pragma unroll
    for (int w8 = 0; w8 < 8; w8++) tot += base[w8 * 128];
    atomicAdd(&g_stats[tidx], tot);
}

// ---------------------------------------------------------------------------
// Kernel 6: finalize — BN + LeakyReLU(0.01), float4 in place.
// Also re-zeroes g_deg for the NEXT invocation (g_off fully consumed by now).
// ---------------------------------------------------------------------------
__global__ __launch_bounds__(256) void final_k(float* __restrict__ out,
                                               const float* __restrict__ gamma,
                                               const float* __restrict__ beta) {
    size_t idx = (size_t)blockIdx.x * blockDim.x + threadIdx.x;     // over N*32
    if (idx < NN) g_deg[idx] = 0;
    if (idx >= (size_t)NN * 32) return;
    int c = (int)(idx & 31) * 4;
    size_t r = idx >> 5;

    float4 v = *(float4*)(out + r * FOUT + c);
    const float invN = 1.0f / NN;
    float y[4] = {v.x, v.y, v.z, v.w};
#pragma unroll
    for (int j = 0; j < 4; j++) {
        int cc = c + j;
        float mu  = g_stats[cc] * invN;
        float var = fmaf(g_stats[128 + cc], invN, -mu * mu);
        float zz = (y[j] - mu) * rsqrtf(var + BN_EPS) * gamma[cc] + beta[cc];
        y[j] = zz < 0.f ? NEG_ACT * zz : zz;
    }
    *(float4*)(out + r * FOUT + c) = make_float4(y[0], y[1], y[2], y[3]);
}

// ---------------------------------------------------------------------------
// Launch: CSR build forked onto a second stream, overlapping the GEMM.
// ---------------------------------------------------------------------------
extern "C" void kernel_launch(void* const* d_in, const int* in_sizes, int n_in,
                              void* d_out, int out_size) {
    const float* x       = (const float*)d_in[0];
    const int*   ei      = (const int*)  d_in[1];
    const float* W       = (const float*)d_in[2];
    const float* att_src = (const float*)d_in[3];
    const float* att_dst = (const float*)d_in[4];
    const float* bias    = (const float*)d_in[5];
    const float* gamma   = (const float*)d_in[6];
    const float* beta    = (const float*)d_in[7];
    float* out = (float*)d_out;

    static cudaStream_t s2 = nullptr;
    static cudaEvent_t  eFork = nullptr, eJoin = nullptr;
    if (!s2) {
        cudaStreamCreateWithFlags(&s2, cudaStreamNonBlocking);
        cudaEventCreateWithFlags(&eFork, cudaEventDisableTiming);
        cudaEventCreateWithFlags(&eJoin, cudaEventDisableTiming);
    }

    cudaEventRecord(eFork, 0);
    cudaStreamWaitEvent(s2, eFork, 0);
    hist_k    <<<(EE + 255) / 256, 256, 0, s2>>>(ei);
    blocksum_k<<<NB, 256, 0, s2>>>();
    scanblk_k <<<1, 256, 0, s2>>>();
    offsets_k <<<NB, 256, 0, s2>>>();
    scatter_k <<<(EE + 255) / 256, 256, 0, s2>>>(ei);
    cudaEventRecord(eJoin, s2);

    gemm_tc<<<(NN + 127) / 128, 256>>>(x, W, att_src, att_dst);

    cudaStreamWaitEvent(0, eJoin, 0);
    agg_k  <<<NN / 8, 256>>>(bias, out);
    final_k<<<(int)(((size_t)NN * 32 + 255) / 256), 256>>>(out, gamma, beta);
}